// round 13
// baseline (speedup 1.0000x reference)
#include <cuda_runtime.h>
#include <cuda_fp16.h>
#include <cstdint>

#define Bq 2
#define Tq 2048
#define Dq 1024
#define Hq 16
#define Sq 16
#define HDq 64
#define KF 64   // K/16 for all GEMMs (K=1024)

// ---------------- scratch (static device globals; no allocation) ----------------
__device__ __align__(128) float g_qkv[(size_t)Bq * Tq * 3 * Dq];   // (B*T, 3072)
__device__ __align__(128) float g_centers[Hq * Sq * HDq];
__device__ __align__(128) float g_invvar[Hq * Sq];
__device__ __align__(128) float g_amps[Hq * Sq];
__device__ __align__(128) float g_qw[(size_t)Bq * Hq * Tq * Sq];
__device__ __align__(128) float g_kw[(size_t)Bq * Hq * Tq * Sq];
// V fragments (fp16 hi only): [b][h][kt(32)][ks(4)][nt(8)][lane(32)] uint2{h0,h1}
__device__ __align__(128) uint2 g_vfrag[(size_t)Bq * Hq * 32 * 1024];
// KW fragments: [b][h][kt(32)][nt(8)][lane(32)] uint4{bh0,bh1,bl0,bl1}
__device__ __align__(128) uint4 g_kwfrag[(size_t)Bq * Hq * 32 * 256];
// A-fragments (hi/lo): [mt(256)][ks(64)][lane(32)] uint4 (regs 0..3)
__device__ __align__(128) uint4 g_xfH[256 * 64 * 32];
__device__ __align__(128) uint4 g_xfL[256 * 64 * 32];
__device__ __align__(128) uint4 g_afH[256 * 64 * 32];   // attn fragments (hi only)
// B-fragments: [nt][ks(64)][lane(32)] uint4{h0,h1,l0,l1}
__device__ __align__(128) uint4 g_wqkvf[384 * 64 * 32];
__device__ __align__(128) uint4 g_wof[128 * 64 * 32];

// ---------------- helpers ----------------
__device__ __forceinline__ void mma_f16(float* c, const uint32_t* a, const uint32_t* b) {
    asm volatile(
        "mma.sync.aligned.m16n8k16.row.col.f32.f16.f16.f32 "
        "{%0,%1,%2,%3}, {%4,%5,%6,%7}, {%8,%9}, {%0,%1,%2,%3};"
        : "+f"(c[0]), "+f"(c[1]), "+f"(c[2]), "+f"(c[3])
        : "r"(a[0]), "r"(a[1]), "r"(a[2]), "r"(a[3]), "r"(b[0]), "r"(b[1]));
}

// pack {low half = x (even k), high half = y (odd k)} as fp16x2
__device__ __forceinline__ uint32_t pack_f16x2(float x, float y) {
    uint32_t r;
    asm("cvt.rn.f16x2.f32 %0, %1, %2;" : "=r"(r) : "f"(y), "f"(x));
    return r;
}
// hi = fp16 pair of (x,y); lo = fp16 pair of residuals
__device__ __forceinline__ void split2(float x, float y, uint32_t& hi, uint32_t& lo) {
    hi = pack_f16x2(x, y);
    __half2 h = *reinterpret_cast<__half2*>(&hi);
    lo = pack_f16x2(x - __half2float(__low2half(h)), y - __half2float(__high2half(h)));
}
__device__ __forceinline__ float ex2_approx(float x) {
    float r;
    asm("ex2.approx.ftz.f32 %0, %1;" : "=f"(r) : "f"(x));
    return r;
}

// ---------------- prep ----------------
__global__ void prep_kernel(const float* __restrict__ centers_in,
                            const float* __restrict__ deltas,
                            const float* __restrict__ log_scales,
                            const float* __restrict__ log_amps,
                            const float* __restrict__ movement_scale) {
    int tid = threadIdx.x;
    float ms = *movement_scale;
    float sig = 1.0f / (1.0f + expf(-ms));
    int i = blockIdx.x * 256 + tid;
    g_centers[i] = centers_in[i] + deltas[i] * sig * 0.2f;
    if (blockIdx.x == 0) {
        float sc = expf(log_scales[tid]);
        sc = fminf(fmaxf(sc, 0.01f), 2.0f);
        g_invvar[tid] = -0.5f / (sc * sc + 1e-8f);
        float am = expf(log_amps[tid]);
        g_amps[tid] = fminf(fmaxf(am, 1e-6f), 10.0f);
    }
}

// ---------------- prepack: fp32 matrix -> A-fragments (hi/lo) ----------------
__global__ __launch_bounds__(256) void a_frag_prepack(const float* __restrict__ A,
                                                      uint4* __restrict__ HF,
                                                      uint4* __restrict__ LF, int K) {
    const int mt = blockIdx.x;
    const int ks = blockIdx.y * 8 + (threadIdx.x >> 5);
    const int lane = threadIdx.x & 31;
    const int r0 = mt * 16 + (lane >> 2);
    const int k0 = ks * 16 + (lane & 3) * 2;
    const float* base = A + (size_t)r0 * K + k0;
    float2 v0 = *(const float2*)base;
    float2 v1 = *(const float2*)(base + 8 * (size_t)K);
    float2 v2 = *(const float2*)(base + 8);
    float2 v3 = *(const float2*)(base + 8 * (size_t)K + 8);
    uint32_t h0, l0, h1, l1, h2, l2, h3, l3;
    split2(v0.x, v0.y, h0, l0);
    split2(v1.x, v1.y, h1, l1);
    split2(v2.x, v2.y, h2, l2);
    split2(v3.x, v3.y, h3, l3);
    size_t idx = ((size_t)mt * KF + ks) * 32 + lane;
    HF[idx] = make_uint4(h0, h1, h2, h3);
    LF[idx] = make_uint4(l0, l1, l2, l3);
}

// ---------------- prepack: fp32 matrix (rows=N of NT gemm) -> B-fragments ----------------
__global__ __launch_bounds__(256) void b_frag_prepack(const float* __restrict__ B,
                                                      uint4* __restrict__ F, int K) {
    const int nt = blockIdx.x;
    const int ks = blockIdx.y * 8 + (threadIdx.x >> 5);
    const int lane = threadIdx.x & 31;
    const int row = nt * 8 + (lane >> 2);
    const int k0 = ks * 16 + (lane & 3) * 2;
    const float* base = B + (size_t)row * K + k0;
    float2 v0 = *(const float2*)base;
    float2 v1 = *(const float2*)(base + 8);
    uint32_t h0, l0, h1, l1;
    split2(v0.x, v0.y, h0, l0);
    split2(v1.x, v1.y, h1, l1);
    F[((size_t)nt * KF + ks) * 32 + lane] = make_uint4(h0, h1, l0, l1);
}

// ---------------- GEMM over prepacked fragments: 512 threads, 2x4 warp tile ----------------
// 16 warps as 4x4; warp tile 32x32 of the 128x128 block tile. ~110 regs ->
// one 512-thread block/SM = 4 warps/SMSP (2x R12's GEMM). Prefetch kept from R10.
__global__ __launch_bounds__(512, 1) void mma_gemm_frag(const uint4* __restrict__ AfH,
                                                        const uint4* __restrict__ AfL,
                                                        const uint4* __restrict__ Bf,
                                                        float* __restrict__ C, int M,
                                                        int vsplit_bx) {
    const int warp = threadIdx.x >> 5;
    const int lane = threadIdx.x & 31;
    const int wm = warp >> 2;          // 0..3
    const int wn = warp & 3;           // 0..3
    const int mt0 = blockIdx.y * 8 + wm * 2;
    const int nt0 = blockIdx.x * 16 + wn * 4;
    const bool three = (int)blockIdx.x < vsplit_bx;

    float acc[2][4][4];
#pragma unroll
    for (int i = 0; i < 2; i++)
#pragma unroll
        for (int j = 0; j < 4; j++)
#pragma unroll
            for (int r = 0; r < 4; r++) acc[i][j][r] = 0.f;

    const uint4* aH = AfH + ((size_t)mt0 * KF) * 32 + lane;
    const uint4* aL = AfL + ((size_t)mt0 * KF) * 32 + lane;
    const uint4* bp = Bf + ((size_t)nt0 * KF) * 32 + lane;
    const int AST = KF * 32;

    uint4 ah[2], al[2], bb[4];
#pragma unroll
    for (int i = 0; i < 2; i++) ah[i] = __ldg(aH + i * AST);
    if (three) {
#pragma unroll
        for (int i = 0; i < 2; i++) al[i] = __ldg(aL + i * AST);
    }
#pragma unroll
    for (int j = 0; j < 4; j++) bb[j] = __ldg(bp + j * AST);

    for (int ks = 0; ks < KF; ks++) {
        uint4 nah[2], nal[2], nbb[4];
        if (ks + 1 < KF) {
#pragma unroll
            for (int i = 0; i < 2; i++) nah[i] = __ldg(aH + i * AST + (ks + 1) * 32);
            if (three) {
#pragma unroll
                for (int i = 0; i < 2; i++) nal[i] = __ldg(aL + i * AST + (ks + 1) * 32);
            }
#pragma unroll
            for (int j = 0; j < 4; j++) nbb[j] = __ldg(bp + j * AST + (ks + 1) * 32);
        }

#pragma unroll
        for (int i = 0; i < 2; i++) {
            uint32_t Ah[4] = {ah[i].x, ah[i].y, ah[i].z, ah[i].w};
#pragma unroll
            for (int j = 0; j < 4; j++) {
                uint32_t Bh[2] = {bb[j].x, bb[j].y};
                uint32_t Bl[2] = {bb[j].z, bb[j].w};
                mma_f16(acc[i][j], Ah, Bh);
                mma_f16(acc[i][j], Ah, Bl);
            }
            if (three) {
                uint32_t Al[4] = {al[i].x, al[i].y, al[i].z, al[i].w};
#pragma unroll
                for (int j = 0; j < 4; j++) {
                    uint32_t Bh[2] = {bb[j].x, bb[j].y};
                    mma_f16(acc[i][j], Al, Bh);
                }
            }
        }

        if (ks + 1 < KF) {
#pragma unroll
            for (int i = 0; i < 2; i++) ah[i] = nah[i];
            if (three) {
#pragma unroll
                for (int i = 0; i < 2; i++) al[i] = nal[i];
            }
#pragma unroll
            for (int j = 0; j < 4; j++) bb[j] = nbb[j];
        }
    }

#pragma unroll
    for (int i = 0; i < 2; i++) {
        int row0 = (mt0 + i) * 16 + (lane >> 2);
#pragma unroll
        for (int j = 0; j < 4; j++) {
            int col = (nt0 + j) * 8 + (lane & 3) * 2;
            *(float2*)(C + (size_t)row0 * M + col) = make_float2(acc[i][j][0], acc[i][j][1]);
            *(float2*)(C + (size_t)(row0 + 8) * M + col) = make_float2(acc[i][j][2], acc[i][j][3]);
        }
    }
}

// ---------------- splat gaussian weights ----------------
__global__ __launch_bounds__(256) void splat_weights_kernel() {
    __shared__ float sx[16][68];
    __shared__ float sc[16][68];
    const int tid = threadIdx.x;
    const int tb = blockIdx.x;
    const int h = blockIdx.y;
    const int b = blockIdx.z >> 1;
    const int which = blockIdx.z & 1;

    const int row = tid >> 4;
    const int d4 = (tid & 15) << 2;

    const int t = tb * 16 + row;
    float4 xv = *(const float4*)(g_qkv + ((size_t)(b * Tq + t) * 3 + which) * Dq + h * HDq + d4);
    *(float4*)&sx[row][d4] = xv;
    float4 cv = *(const float4*)(g_centers + (h * Sq + row) * HDq + d4);
    *(float4*)&sc[row][d4] = cv;
    __syncthreads();

    const int s = tid & 15;
    const int ti = tid >> 4;
    float acc = 0.f;
#pragma unroll
    for (int d = 0; d < 64; d++) {
        float diff = sx[ti][d] - sc[s][d];
        acc += diff * diff;
    }
    float w = __expf(acc * g_invvar[h * Sq + s]);
    if (which) w *= g_amps[h * Sq + s];
    float* dst = which ? g_kw : g_qw;
    dst[(((size_t)b * Hq + h) * Tq + (tb * 16 + ti)) * Sq + s] = w;
}

// ---------------- V fragment precompute (fp16 hi only) ----------------
__global__ __launch_bounds__(256) void v_frag_kernel() {
    __shared__ float sv[64][68];
    const int kt = blockIdx.x, h = blockIdx.y, b = blockIdx.z;
    const int tid = threadIdx.x;

#pragma unroll
    for (int i = 0; i < 4; i++) {
        int idx = i * 256 + tid;
        int row = idx >> 4;
        int c4 = (idx & 15) << 2;
        float4 v = *(const float4*)(g_qkv + ((size_t)(b * Tq + kt * 64 + row) * 3 + 2) * Dq +
                                    h * 64 + c4);
        *(float4*)&sv[row][c4] = v;
    }
    __syncthreads();

    uint2* dst = g_vfrag + (((size_t)(b * Hq + h) * 32 + kt) << 10);
#pragma unroll
    for (int i = 0; i < 4; i++) {
        int w = i * 256 + tid;
        int ks = w >> 8, rest = w & 255, nt = rest >> 5, lane = rest & 31;
        int d = nt * 8 + (lane >> 2);
        int k0 = ks * 16 + (lane & 3) * 2;
        uint32_t h0 = pack_f16x2(sv[k0][d], sv[k0 + 1][d]);
        uint32_t h1 = pack_f16x2(sv[k0 + 8][d], sv[k0 + 9][d]);
        dst[w] = make_uint2(h0, h1);
    }
}

// ---------------- KW fragment precompute ----------------
__global__ __launch_bounds__(256) void kw_frag_kernel() {
    const int kt = blockIdx.x, h = blockIdx.y, b = blockIdx.z;
    const int tid = threadIdx.x;
    const int nt = tid >> 5, lane = tid & 31;
    const float* kw = g_kw + (((size_t)b * Hq + h) * Tq + kt * 64 + nt * 8 + (lane >> 2)) * Sq;
    const int s0 = (lane & 3) * 2;
    uint32_t h0, l0, h1, l1;
    split2(__ldg(kw + s0), __ldg(kw + s0 + 1), h0, l0);
    split2(__ldg(kw + s0 + 8), __ldg(kw + s0 + 9), h1, l1);
    g_kwfrag[(((size_t)(b * Hq + h) * 32 + kt) << 8) + tid] = make_uint4(h0, h1, l0, l1);
}

// ---------------- flash attention: 1 query tile per warp (R12 exact) ----------------
__global__ __launch_bounds__(128, 6) void flash_mma(const float* __restrict__ temperature) {
    const int tid = threadIdx.x;
    const int warp = tid >> 5;
    const int lane = tid & 31;
    const int qt = blockIdx.x, h = blockIdx.y, b = blockIdx.z;

    const float temp = fminf(fmaxf(*temperature, 0.1f), 10.0f);
    const float LOG2E = 1.4426950408889634f;
    const float qscale = LOG2E / temp;
    float asum = 0.f;
#pragma unroll
    for (int s = 0; s < 16; s++) asum += g_amps[h * 16 + s];
    const float bound2 = asum * qscale;
    const float off2 = fmaxf(bound2 - 10.0f, 0.f);   // p = 2^(l2-off2) <= 2^10, fp16-safe

    const int r = lane >> 2;
    const int scp = (lane & 3) << 1;
    const int q0 = qt * 64 + warp * 16 + r;

    uint32_t qhi[4], qlo[4];
    {
        const float* qwp = g_qw + (((size_t)b * Hq + h) * Tq + q0) * Sq;
        float2 v;
        v = *(const float2*)(qwp + scp);
        split2(v.x * qscale, v.y * qscale, qhi[0], qlo[0]);
        v = *(const float2*)(qwp + 8 * Sq + scp);
        split2(v.x * qscale, v.y * qscale, qhi[1], qlo[1]);
        v = *(const float2*)(qwp + scp + 8);
        split2(v.x * qscale, v.y * qscale, qhi[2], qlo[2]);
        v = *(const float2*)(qwp + 8 * Sq + scp + 8);
        split2(v.x * qscale, v.y * qscale, qhi[3], qlo[3]);
    }

    float acc[8][4];
#pragma unroll
    for (int nt = 0; nt < 8; nt++)
#pragma unroll
        for (int i = 0; i < 4; i++) acc[nt][i] = 0.f;
    float ls0 = 0.f, ls1 = 0.f;

    const uint4* kwf = g_kwfrag + (((size_t)(b * Hq + h)) << 13) + lane;
    const uint2* vfb = g_vfrag + (((size_t)(b * Hq + h)) << 15) + lane;

    for (int kt = 0; kt < 32; kt++) {
        const uint4* kf = kwf + kt * 256;
        const uint2* vf = vfb + kt * 1024;
#pragma unroll
        for (int ks = 0; ks < 4; ks++) {
            uint32_t ap[4];
#pragma unroll
            for (int ntl = 0; ntl < 2; ntl++) {
                uint4 f = __ldg(kf + (ks * 2 + ntl) * 32);
                uint32_t bh[2] = {f.x, f.y};
                uint32_t bl[2] = {f.z, f.w};
                float c4[4] = {0.f, 0.f, 0.f, 0.f};
                mma_f16(c4, qhi, bh);
                mma_f16(c4, qhi, bl);
                mma_f16(c4, qlo, bh);
                float p0 = ex2_approx(c4[0] - off2);
                float p1 = ex2_approx(c4[1] - off2);
                float p2 = ex2_approx(c4[2] - off2);
                float p3 = ex2_approx(c4[3] - off2);
                ls0 += p0 + p1;
                ls1 += p2 + p3;
                ap[ntl * 2] = pack_f16x2(p0, p1);
                ap[ntl * 2 + 1] = pack_f16x2(p2, p3);
            }
#pragma unroll
            for (int nt = 0; nt < 8; nt++) {
                uint2 f = __ldg(vf + (ks * 8 + nt) * 32);
                uint32_t bh2[2] = {f.x, f.y};
                mma_f16(acc[nt], ap, bh2);
            }
        }
    }

    ls0 += __shfl_xor_sync(0xffffffffu, ls0, 1);
    ls0 += __shfl_xor_sync(0xffffffffu, ls0, 2);
    ls1 += __shfl_xor_sync(0xffffffffu, ls1, 1);
    ls1 += __shfl_xor_sync(0xffffffffu, ls1, 2);
    float inv0 = 1.0f / ls0, inv1 = 1.0f / ls1;

    // emit attn (hi-only fp16) in A-fragment order for the out-GEMM
    int mt = b * 128 + qt * 4 + warp;
#pragma unroll
    for (int ks = 0; ks < 4; ks++) {
        uint32_t h0 = pack_f16x2(acc[2 * ks][0] * inv0, acc[2 * ks][1] * inv0);
        uint32_t h1 = pack_f16x2(acc[2 * ks][2] * inv1, acc[2 * ks][3] * inv1);
        uint32_t h2 = pack_f16x2(acc[2 * ks + 1][0] * inv0, acc[2 * ks + 1][1] * inv0);
        uint32_t h3 = pack_f16x2(acc[2 * ks + 1][2] * inv1, acc[2 * ks + 1][3] * inv1);
        size_t idx = ((size_t)mt * KF + h * 4 + ks) * 32 + lane;
        g_afH[idx] = make_uint4(h0, h1, h2, h3);
    }
}

// ---------------- launch ----------------
extern "C" void kernel_launch(void* const* d_in, const int* in_sizes, int n_in,
                              void* d_out, int out_size) {
    const float* x           = (const float*)d_in[0];
    const float* centers     = (const float*)d_in[1];
    const float* deltas      = (const float*)d_in[2];
    const float* log_scales  = (const float*)d_in[3];
    const float* log_amps    = (const float*)d_in[4];
    const float* movement    = (const float*)d_in[5];
    const float* temperature = (const float*)d_in[6];
    const float* qkv_w       = (const float*)d_in[7];
    const float* out_w       = (const float*)d_in[8];
    float* out = (float*)d_out;

    void *p_qkv = nullptr, *p_xfH = nullptr, *p_xfL = nullptr, *p_afH = nullptr,
         *p_wqkv = nullptr, *p_wo = nullptr;
    cudaGetSymbolAddress(&p_qkv, g_qkv);
    cudaGetSymbolAddress(&p_xfH, g_xfH);
    cudaGetSymbolAddress(&p_xfL, g_xfL);
    cudaGetSymbolAddress(&p_afH, g_afH);
    cudaGetSymbolAddress(&p_wqkv, g_wqkvf);
    cudaGetSymbolAddress(&p_wo, g_wof);
    float* qkv_buf = (float*)p_qkv;

    prep_kernel<<<64, 256>>>(centers, deltas, log_scales, log_amps, movement);

    // prepack fragments
    a_frag_prepack<<<dim3(256, 8), 256>>>(x, (uint4*)p_xfH, (uint4*)p_xfL, Dq);
    b_frag_prepack<<<dim3(384, 8), 256>>>(qkv_w, (uint4*)p_wqkv, Dq);
    b_frag_prepack<<<dim3(128, 8), 256>>>(out_w, (uint4*)p_wo, Dq);

    // qkv = x @ qkv_w.T : q,k cols 3-product (blocks 0..15); v cols 2-product
    mma_gemm_frag<<<dim3(3072 / 128, 4096 / 128), 512>>>(
        (const uint4*)p_xfH, (const uint4*)p_xfL, (const uint4*)p_wqkv, qkv_buf, 3 * Dq, 16);

    v_frag_kernel<<<dim3(32, Hq, Bq), 256>>>();
    splat_weights_kernel<<<dim3(Tq / 16, Hq, Bq * 2), 256>>>();
    kw_frag_kernel<<<dim3(32, Hq, Bq), 256>>>();

    flash_mma<<<dim3(Tq / 64, Hq, Bq), 128>>>(temperature);

    // out = attn @ out_w.T : all 2-product (A hi-only from flash)
    mma_gemm_frag<<<dim3(1024 / 128, 4096 / 128), 512>>>(
        (const uint4*)p_afH, (const uint4*)p_afH, (const uint4*)p_wo, out, Dq, 0);
}

// round 14
// speedup vs baseline: 1.0794x; 1.0794x over previous
#include <cuda_runtime.h>
#include <cuda_fp16.h>
#include <cstdint>

#define Bq 2
#define Tq 2048
#define Dq 1024
#define Hq 16
#define Sq 16
#define HDq 64
#define KF 64   // K/16 for all GEMMs (K=1024)

// ---------------- scratch (static device globals; no allocation) ----------------
__device__ __align__(128) float g_qkv[(size_t)Bq * Tq * 3 * Dq];   // (B*T, 3072)
__device__ __align__(128) float g_centers[Hq * Sq * HDq];
__device__ __align__(128) float g_invvar[Hq * Sq];
__device__ __align__(128) float g_amps[Hq * Sq];
__device__ __align__(128) float g_qw[(size_t)Bq * Hq * Tq * Sq];
__device__ __align__(128) float g_kw[(size_t)Bq * Hq * Tq * Sq];
// V fragments (fp16 hi only): [b][h][kt(32)][ks(4)][nt(8)][lane(32)] uint2{h0,h1}
__device__ __align__(128) uint2 g_vfrag[(size_t)Bq * Hq * 32 * 1024];
// KW fragments: [b][h][kt(32)][nt(8)][lane(32)] uint4{bh0,bh1,bl0,bl1}
__device__ __align__(128) uint4 g_kwfrag[(size_t)Bq * Hq * 32 * 256];
// A-fragments (hi/lo): [mt(256)][ks(64)][lane(32)] uint4 (regs 0..3)
__device__ __align__(128) uint4 g_xfH[256 * 64 * 32];
__device__ __align__(128) uint4 g_xfL[256 * 64 * 32];
__device__ __align__(128) uint4 g_afH[256 * 64 * 32];   // attn fragments (hi only)
// B-fragments: [nt][ks(64)][lane(32)] uint4{h0,h1,l0,l1}
__device__ __align__(128) uint4 g_wqkvf[384 * 64 * 32];
__device__ __align__(128) uint4 g_wof[128 * 64 * 32];

// ---------------- helpers ----------------
__device__ __forceinline__ void mma_f16(float* c, const uint32_t* a, const uint32_t* b) {
    asm volatile(
        "mma.sync.aligned.m16n8k16.row.col.f32.f16.f16.f32 "
        "{%0,%1,%2,%3}, {%4,%5,%6,%7}, {%8,%9}, {%0,%1,%2,%3};"
        : "+f"(c[0]), "+f"(c[1]), "+f"(c[2]), "+f"(c[3])
        : "r"(a[0]), "r"(a[1]), "r"(a[2]), "r"(a[3]), "r"(b[0]), "r"(b[1]));
}

// pack {low half = x (even k), high half = y (odd k)} as fp16x2
__device__ __forceinline__ uint32_t pack_f16x2(float x, float y) {
    uint32_t r;
    asm("cvt.rn.f16x2.f32 %0, %1, %2;" : "=r"(r) : "f"(y), "f"(x));
    return r;
}
// hi = fp16 pair of (x,y); lo = fp16 pair of residuals
__device__ __forceinline__ void split2(float x, float y, uint32_t& hi, uint32_t& lo) {
    hi = pack_f16x2(x, y);
    __half2 h = *reinterpret_cast<__half2*>(&hi);
    lo = pack_f16x2(x - __half2float(__low2half(h)), y - __half2float(__high2half(h)));
}
__device__ __forceinline__ float ex2_approx(float x) {
    float r;
    asm("ex2.approx.ftz.f32 %0, %1;" : "=f"(r) : "f"(x));
    return r;
}

// ---------------- prep ----------------
__global__ void prep_kernel(const float* __restrict__ centers_in,
                            const float* __restrict__ deltas,
                            const float* __restrict__ log_scales,
                            const float* __restrict__ log_amps,
                            const float* __restrict__ movement_scale) {
    int tid = threadIdx.x;
    float ms = *movement_scale;
    float sig = 1.0f / (1.0f + expf(-ms));
    int i = blockIdx.x * 256 + tid;
    g_centers[i] = centers_in[i] + deltas[i] * sig * 0.2f;
    if (blockIdx.x == 0) {
        float sc = expf(log_scales[tid]);
        sc = fminf(fmaxf(sc, 0.01f), 2.0f);
        g_invvar[tid] = -0.5f / (sc * sc + 1e-8f);
        float am = expf(log_amps[tid]);
        g_amps[tid] = fminf(fmaxf(am, 1e-6f), 10.0f);
    }
}

// ---------------- prepack: fp32 matrix -> A-fragments (hi/lo) ----------------
__global__ __launch_bounds__(256) void a_frag_prepack(const float* __restrict__ A,
                                                      uint4* __restrict__ HF,
                                                      uint4* __restrict__ LF, int K) {
    const int mt = blockIdx.x;
    const int ks = blockIdx.y * 8 + (threadIdx.x >> 5);
    const int lane = threadIdx.x & 31;
    const int r0 = mt * 16 + (lane >> 2);
    const int k0 = ks * 16 + (lane & 3) * 2;
    const float* base = A + (size_t)r0 * K + k0;
    float2 v0 = *(const float2*)base;
    float2 v1 = *(const float2*)(base + 8 * (size_t)K);
    float2 v2 = *(const float2*)(base + 8);
    float2 v3 = *(const float2*)(base + 8 * (size_t)K + 8);
    uint32_t h0, l0, h1, l1, h2, l2, h3, l3;
    split2(v0.x, v0.y, h0, l0);
    split2(v1.x, v1.y, h1, l1);
    split2(v2.x, v2.y, h2, l2);
    split2(v3.x, v3.y, h3, l3);
    size_t idx = ((size_t)mt * KF + ks) * 32 + lane;
    HF[idx] = make_uint4(h0, h1, h2, h3);
    LF[idx] = make_uint4(l0, l1, l2, l3);
}

// ---------------- prepack: fp32 matrix (rows=N of NT gemm) -> B-fragments ----------------
__global__ __launch_bounds__(256) void b_frag_prepack(const float* __restrict__ B,
                                                      uint4* __restrict__ F, int K) {
    const int nt = blockIdx.x;
    const int ks = blockIdx.y * 8 + (threadIdx.x >> 5);
    const int lane = threadIdx.x & 31;
    const int row = nt * 8 + (lane >> 2);
    const int k0 = ks * 16 + (lane & 3) * 2;
    const float* base = B + (size_t)row * K + k0;
    float2 v0 = *(const float2*)base;
    float2 v1 = *(const float2*)(base + 8);
    uint32_t h0, l0, h1, l1;
    split2(v0.x, v0.y, h0, l0);
    split2(v1.x, v1.y, h1, l1);
    F[((size_t)nt * KF + ks) * 32 + lane] = make_uint4(h0, h1, l0, l1);
}

// ---------------- GEMM over prepacked fragments (R10/R12: 256 thr, 4x4, prefetch) ----------------
__global__ __launch_bounds__(256, 1) void mma_gemm_frag(const uint4* __restrict__ AfH,
                                                        const uint4* __restrict__ AfL,
                                                        const uint4* __restrict__ Bf,
                                                        float* __restrict__ C, int M,
                                                        int vsplit_bx) {
    const int warp = threadIdx.x >> 5;
    const int lane = threadIdx.x & 31;
    const int wm = warp >> 2;
    const int wn = warp & 3;
    const int mt0 = blockIdx.y * 8 + wm * 4;
    const int nt0 = blockIdx.x * 16 + wn * 4;
    const bool three = (int)blockIdx.x < vsplit_bx;

    float acc[4][4][4];
#pragma unroll
    for (int i = 0; i < 4; i++)
#pragma unroll
        for (int j = 0; j < 4; j++)
#pragma unroll
            for (int r = 0; r < 4; r++) acc[i][j][r] = 0.f;

    const uint4* aH = AfH + ((size_t)mt0 * KF) * 32 + lane;
    const uint4* aL = AfL + ((size_t)mt0 * KF) * 32 + lane;
    const uint4* bp = Bf + ((size_t)nt0 * KF) * 32 + lane;
    const int AST = KF * 32;

    uint4 ah[4], al[4], bb[4];
#pragma unroll
    for (int i = 0; i < 4; i++) ah[i] = __ldg(aH + i * AST);
    if (three) {
#pragma unroll
        for (int i = 0; i < 4; i++) al[i] = __ldg(aL + i * AST);
    }
#pragma unroll
    for (int j = 0; j < 4; j++) bb[j] = __ldg(bp + j * AST);

    for (int ks = 0; ks < KF; ks++) {
        uint4 nah[4], nal[4], nbb[4];
        if (ks + 1 < KF) {
#pragma unroll
            for (int i = 0; i < 4; i++) nah[i] = __ldg(aH + i * AST + (ks + 1) * 32);
            if (three) {
#pragma unroll
                for (int i = 0; i < 4; i++) nal[i] = __ldg(aL + i * AST + (ks + 1) * 32);
            }
#pragma unroll
            for (int j = 0; j < 4; j++) nbb[j] = __ldg(bp + j * AST + (ks + 1) * 32);
        }

#pragma unroll
        for (int i = 0; i < 4; i++) {
            uint32_t Ah[4] = {ah[i].x, ah[i].y, ah[i].z, ah[i].w};
#pragma unroll
            for (int j = 0; j < 4; j++) {
                uint32_t Bh[2] = {bb[j].x, bb[j].y};
                uint32_t Bl[2] = {bb[j].z, bb[j].w};
                mma_f16(acc[i][j], Ah, Bh);
                mma_f16(acc[i][j], Ah, Bl);
            }
            if (three) {
                uint32_t Al[4] = {al[i].x, al[i].y, al[i].z, al[i].w};
#pragma unroll
                for (int j = 0; j < 4; j++) {
                    uint32_t Bh[2] = {bb[j].x, bb[j].y};
                    mma_f16(acc[i][j], Al, Bh);
                }
            }
        }

        if (ks + 1 < KF) {
#pragma unroll
            for (int i = 0; i < 4; i++) ah[i] = nah[i];
            if (three) {
#pragma unroll
                for (int i = 0; i < 4; i++) al[i] = nal[i];
            }
#pragma unroll
            for (int j = 0; j < 4; j++) bb[j] = nbb[j];
        }
    }

#pragma unroll
    for (int i = 0; i < 4; i++) {
        int row0 = (mt0 + i) * 16 + (lane >> 2);
#pragma unroll
        for (int j = 0; j < 4; j++) {
            int col = (nt0 + j) * 8 + (lane & 3) * 2;
            *(float2*)(C + (size_t)row0 * M + col) = make_float2(acc[i][j][0], acc[i][j][1]);
            *(float2*)(C + (size_t)(row0 + 8) * M + col) = make_float2(acc[i][j][2], acc[i][j][3]);
        }
    }
}

// ---------------- splat gaussian weights ----------------
__global__ __launch_bounds__(256) void splat_weights_kernel() {
    __shared__ float sx[16][68];
    __shared__ float sc[16][68];
    const int tid = threadIdx.x;
    const int tb = blockIdx.x;
    const int h = blockIdx.y;
    const int b = blockIdx.z >> 1;
    const int which = blockIdx.z & 1;

    const int row = tid >> 4;
    const int d4 = (tid & 15) << 2;

    const int t = tb * 16 + row;
    float4 xv = *(const float4*)(g_qkv + ((size_t)(b * Tq + t) * 3 + which) * Dq + h * HDq + d4);
    *(float4*)&sx[row][d4] = xv;
    float4 cv = *(const float4*)(g_centers + (h * Sq + row) * HDq + d4);
    *(float4*)&sc[row][d4] = cv;
    __syncthreads();

    const int s = tid & 15;
    const int ti = tid >> 4;
    float acc = 0.f;
#pragma unroll
    for (int d = 0; d < 64; d++) {
        float diff = sx[ti][d] - sc[s][d];
        acc += diff * diff;
    }
    float w = __expf(acc * g_invvar[h * Sq + s]);
    if (which) w *= g_amps[h * Sq + s];
    float* dst = which ? g_kw : g_qw;
    dst[(((size_t)b * Hq + h) * Tq + (tb * 16 + ti)) * Sq + s] = w;
}

// ---------------- V fragment precompute (fp16 hi only) ----------------
__global__ __launch_bounds__(256) void v_frag_kernel() {
    __shared__ float sv[64][68];
    const int kt = blockIdx.x, h = blockIdx.y, b = blockIdx.z;
    const int tid = threadIdx.x;

#pragma unroll
    for (int i = 0; i < 4; i++) {
        int idx = i * 256 + tid;
        int row = idx >> 4;
        int c4 = (idx & 15) << 2;
        float4 v = *(const float4*)(g_qkv + ((size_t)(b * Tq + kt * 64 + row) * 3 + 2) * Dq +
                                    h * 64 + c4);
        *(float4*)&sv[row][c4] = v;
    }
    __syncthreads();

    uint2* dst = g_vfrag + (((size_t)(b * Hq + h) * 32 + kt) << 10);
#pragma unroll
    for (int i = 0; i < 4; i++) {
        int w = i * 256 + tid;
        int ks = w >> 8, rest = w & 255, nt = rest >> 5, lane = rest & 31;
        int d = nt * 8 + (lane >> 2);
        int k0 = ks * 16 + (lane & 3) * 2;
        uint32_t h0 = pack_f16x2(sv[k0][d], sv[k0 + 1][d]);
        uint32_t h1 = pack_f16x2(sv[k0 + 8][d], sv[k0 + 9][d]);
        dst[w] = make_uint2(h0, h1);
    }
}

// ---------------- KW fragment precompute ----------------
__global__ __launch_bounds__(256) void kw_frag_kernel() {
    const int kt = blockIdx.x, h = blockIdx.y, b = blockIdx.z;
    const int tid = threadIdx.x;
    const int nt = tid >> 5, lane = tid & 31;
    const float* kw = g_kw + (((size_t)b * Hq + h) * Tq + kt * 64 + nt * 8 + (lane >> 2)) * Sq;
    const int s0 = (lane & 3) * 2;
    uint32_t h0, l0, h1, l1;
    split2(__ldg(kw + s0), __ldg(kw + s0 + 1), h0, l0);
    split2(__ldg(kw + s0 + 8), __ldg(kw + s0 + 9), h1, l1);
    g_kwfrag[(((size_t)(b * Hq + h) * 32 + kt) << 8) + tid] = make_uint4(h0, h1, l0, l1);
}

// ---------------- flash attention: 1 query tile per warp (R12 exact) ----------------
__global__ __launch_bounds__(128, 6) void flash_mma(const float* __restrict__ temperature) {
    const int tid = threadIdx.x;
    const int warp = tid >> 5;
    const int lane = tid & 31;
    const int qt = blockIdx.x, h = blockIdx.y, b = blockIdx.z;

    const float temp = fminf(fmaxf(*temperature, 0.1f), 10.0f);
    const float LOG2E = 1.4426950408889634f;
    const float qscale = LOG2E / temp;
    float asum = 0.f;
#pragma unroll
    for (int s = 0; s < 16; s++) asum += g_amps[h * 16 + s];
    const float bound2 = asum * qscale;
    const float off2 = fmaxf(bound2 - 10.0f, 0.f);   // p = 2^(l2-off2) <= 2^10, fp16-safe

    const int r = lane >> 2;
    const int scp = (lane & 3) << 1;
    const int q0 = qt * 64 + warp * 16 + r;

    uint32_t qhi[4], qlo[4];
    {
        const float* qwp = g_qw + (((size_t)b * Hq + h) * Tq + q0) * Sq;
        float2 v;
        v = *(const float2*)(qwp + scp);
        split2(v.x * qscale, v.y * qscale, qhi[0], qlo[0]);
        v = *(const float2*)(qwp + 8 * Sq + scp);
        split2(v.x * qscale, v.y * qscale, qhi[1], qlo[1]);
        v = *(const float2*)(qwp + scp + 8);
        split2(v.x * qscale, v.y * qscale, qhi[2], qlo[2]);
        v = *(const float2*)(qwp + 8 * Sq + scp + 8);
        split2(v.x * qscale, v.y * qscale, qhi[3], qlo[3]);
    }

    float acc[8][4];
#pragma unroll
    for (int nt = 0; nt < 8; nt++)
#pragma unroll
        for (int i = 0; i < 4; i++) acc[nt][i] = 0.f;
    float ls0 = 0.f, ls1 = 0.f;

    const uint4* kwf = g_kwfrag + (((size_t)(b * Hq + h)) << 13) + lane;
    const uint2* vfb = g_vfrag + (((size_t)(b * Hq + h)) << 15) + lane;

    for (int kt = 0; kt < 32; kt++) {
        const uint4* kf = kwf + kt * 256;
        const uint2* vf = vfb + kt * 1024;
#pragma unroll
        for (int ks = 0; ks < 4; ks++) {
            uint32_t ap[4];
#pragma unroll
            for (int ntl = 0; ntl < 2; ntl++) {
                uint4 f = __ldg(kf + (ks * 2 + ntl) * 32);
                uint32_t bh[2] = {f.x, f.y};
                uint32_t bl[2] = {f.z, f.w};
                float c4[4] = {0.f, 0.f, 0.f, 0.f};
                mma_f16(c4, qhi, bh);
                mma_f16(c4, qhi, bl);
                mma_f16(c4, qlo, bh);
                float p0 = ex2_approx(c4[0] - off2);
                float p1 = ex2_approx(c4[1] - off2);
                float p2 = ex2_approx(c4[2] - off2);
                float p3 = ex2_approx(c4[3] - off2);
                ls0 += p0 + p1;
                ls1 += p2 + p3;
                ap[ntl * 2] = pack_f16x2(p0, p1);
                ap[ntl * 2 + 1] = pack_f16x2(p2, p3);
            }
#pragma unroll
            for (int nt = 0; nt < 8; nt++) {
                uint2 f = __ldg(vf + (ks * 8 + nt) * 32);
                uint32_t bh2[2] = {f.x, f.y};
                mma_f16(acc[nt], ap, bh2);
            }
        }
    }

    ls0 += __shfl_xor_sync(0xffffffffu, ls0, 1);
    ls0 += __shfl_xor_sync(0xffffffffu, ls0, 2);
    ls1 += __shfl_xor_sync(0xffffffffu, ls1, 1);
    ls1 += __shfl_xor_sync(0xffffffffu, ls1, 2);
    float inv0 = 1.0f / ls0, inv1 = 1.0f / ls1;

    // emit attn (hi-only fp16) in A-fragment order for the out-GEMM
    int mt = b * 128 + qt * 4 + warp;
#pragma unroll
    for (int ks = 0; ks < 4; ks++) {
        uint32_t h0 = pack_f16x2(acc[2 * ks][0] * inv0, acc[2 * ks][1] * inv0);
        uint32_t h1 = pack_f16x2(acc[2 * ks][2] * inv1, acc[2 * ks][3] * inv1);
        uint32_t h2 = pack_f16x2(acc[2 * ks + 1][0] * inv0, acc[2 * ks + 1][1] * inv0);
        uint32_t h3 = pack_f16x2(acc[2 * ks + 1][2] * inv1, acc[2 * ks + 1][3] * inv1);
        size_t idx = ((size_t)mt * KF + h * 4 + ks) * 32 + lane;
        g_afH[idx] = make_uint4(h0, h1, h2, h3);
    }
}

// ---------------- launch ----------------
// Order chosen so the ncu capture slot (empirically the 4th launch) lands on
// mma_gemm_frag (gemm1). Dependencies preserved.
extern "C" void kernel_launch(void* const* d_in, const int* in_sizes, int n_in,
                              void* d_out, int out_size) {
    const float* x           = (const float*)d_in[0];
    const float* centers     = (const float*)d_in[1];
    const float* deltas      = (const float*)d_in[2];
    const float* log_scales  = (const float*)d_in[3];
    const float* log_amps    = (const float*)d_in[4];
    const float* movement    = (const float*)d_in[5];
    const float* temperature = (const float*)d_in[6];
    const float* qkv_w       = (const float*)d_in[7];
    const float* out_w       = (const float*)d_in[8];
    float* out = (float*)d_out;

    void *p_qkv = nullptr, *p_xfH = nullptr, *p_xfL = nullptr, *p_afH = nullptr,
         *p_wqkv = nullptr, *p_wo = nullptr;
    cudaGetSymbolAddress(&p_qkv, g_qkv);
    cudaGetSymbolAddress(&p_xfH, g_xfH);
    cudaGetSymbolAddress(&p_xfL, g_xfL);
    cudaGetSymbolAddress(&p_afH, g_afH);
    cudaGetSymbolAddress(&p_wqkv, g_wqkvf);
    cudaGetSymbolAddress(&p_wo, g_wof);
    float* qkv_buf = (float*)p_qkv;

    // (1) (2) (3): gemm1 prerequisites + prep
    a_frag_prepack<<<dim3(256, 8), 256>>>(x, (uint4*)p_xfH, (uint4*)p_xfL, Dq);
    b_frag_prepack<<<dim3(384, 8), 256>>>(qkv_w, (uint4*)p_wqkv, Dq);
    prep_kernel<<<64, 256>>>(centers, deltas, log_scales, log_amps, movement);

    // (4) gemm1 — profiled slot
    mma_gemm_frag<<<dim3(3072 / 128, 4096 / 128), 256>>>(
        (const uint4*)p_xfH, (const uint4*)p_xfL, (const uint4*)p_wqkv, qkv_buf, 3 * Dq, 16);

    // (5)+ rest
    b_frag_prepack<<<dim3(128, 8), 256>>>(out_w, (uint4*)p_wo, Dq);
    v_frag_kernel<<<dim3(32, Hq, Bq), 256>>>();
    splat_weights_kernel<<<dim3(Tq / 16, Hq, Bq * 2), 256>>>();
    kw_frag_kernel<<<dim3(32, Hq, Bq), 256>>>();

    flash_mma<<<dim3(Tq / 64, Hq, Bq), 128>>>(temperature);

    // out = attn @ out_w.T : all 2-product (A hi-only from flash)
    mma_gemm_frag<<<dim3(1024 / 128, 4096 / 128), 256>>>(
        (const uint4*)p_afH, (const uint4*)p_afH, (const uint4*)p_wo, out, Dq, 0);
}

// round 15
// speedup vs baseline: 1.0952x; 1.0147x over previous
#include <cuda_runtime.h>
#include <cuda_fp16.h>
#include <cstdint>

#define Bq 2
#define Tq 2048
#define Dq 1024
#define Hq 16
#define Sq 16
#define HDq 64
#define KF 64   // K/16 for all GEMMs (K=1024)

// ---------------- scratch (static device globals; no allocation) ----------------
__device__ __align__(128) float g_qkv[(size_t)Bq * Tq * 3 * Dq];   // (B*T, 3072)
__device__ __align__(128) float g_centers[Hq * Sq * HDq];
__device__ __align__(128) float g_invvar[Hq * Sq];
__device__ __align__(128) float g_amps[Hq * Sq];
__device__ __align__(128) float g_qw[(size_t)Bq * Hq * Tq * Sq];
__device__ __align__(128) float g_kw[(size_t)Bq * Hq * Tq * Sq];
// V fragments (fp16 hi only): [b][h][kt(32)][ks(4)][nt(8)][lane(32)] uint2{h0,h1}
__device__ __align__(128) uint2 g_vfrag[(size_t)Bq * Hq * 32 * 1024];
// KW fragments: [b][h][kt(32)][nt(8)][lane(32)] uint4{bh0,bh1,bl0,bl1}
__device__ __align__(128) uint4 g_kwfrag[(size_t)Bq * Hq * 32 * 256];
// A-fragments (hi/lo): [mt(256)][ks(64)][lane(32)] uint4 (regs 0..3)
__device__ __align__(128) uint4 g_xfH[256 * 64 * 32];
__device__ __align__(128) uint4 g_xfL[256 * 64 * 32];
__device__ __align__(128) uint4 g_afH[256 * 64 * 32];   // attn fragments (hi only)
// B-fragments: [nt][ks(64)][lane(32)] uint4{h0,h1,l0,l1}
__device__ __align__(128) uint4 g_wqkvf[384 * 64 * 32];
__device__ __align__(128) uint4 g_wof[128 * 64 * 32];

// ---------------- helpers ----------------
__device__ __forceinline__ void mma_f16(float* c, const uint32_t* a, const uint32_t* b) {
    asm volatile(
        "mma.sync.aligned.m16n8k16.row.col.f32.f16.f16.f32 "
        "{%0,%1,%2,%3}, {%4,%5,%6,%7}, {%8,%9}, {%0,%1,%2,%3};"
        : "+f"(c[0]), "+f"(c[1]), "+f"(c[2]), "+f"(c[3])
        : "r"(a[0]), "r"(a[1]), "r"(a[2]), "r"(a[3]), "r"(b[0]), "r"(b[1]));
}

// pack {low half = x (even k), high half = y (odd k)} as fp16x2
__device__ __forceinline__ uint32_t pack_f16x2(float x, float y) {
    uint32_t r;
    asm("cvt.rn.f16x2.f32 %0, %1, %2;" : "=r"(r) : "f"(y), "f"(x));
    return r;
}
// hi = fp16 pair of (x,y); lo = fp16 pair of residuals
__device__ __forceinline__ void split2(float x, float y, uint32_t& hi, uint32_t& lo) {
    hi = pack_f16x2(x, y);
    __half2 h = *reinterpret_cast<__half2*>(&hi);
    lo = pack_f16x2(x - __half2float(__low2half(h)), y - __half2float(__high2half(h)));
}
__device__ __forceinline__ float ex2_approx(float x) {
    float r;
    asm("ex2.approx.ftz.f32 %0, %1;" : "=f"(r) : "f"(x));
    return r;
}
__device__ __forceinline__ uint32_t smem_u32(const void* p) {
    return (uint32_t)__cvta_generic_to_shared(p);
}
__device__ __forceinline__ void cp_async16(uint32_t saddr, const void* gptr) {
    asm volatile("cp.async.cg.shared.global [%0], [%1], 16;" :: "r"(saddr), "l"(gptr));
}
#define CP_COMMIT() asm volatile("cp.async.commit_group;" ::: "memory")
#define CP_WAIT1() asm volatile("cp.async.wait_group 1;" ::: "memory")

// ---------------- prep ----------------
__global__ void prep_kernel(const float* __restrict__ centers_in,
                            const float* __restrict__ deltas,
                            const float* __restrict__ log_scales,
                            const float* __restrict__ log_amps,
                            const float* __restrict__ movement_scale) {
    int tid = threadIdx.x;
    float ms = *movement_scale;
    float sig = 1.0f / (1.0f + expf(-ms));
    int i = blockIdx.x * 256 + tid;
    g_centers[i] = centers_in[i] + deltas[i] * sig * 0.2f;
    if (blockIdx.x == 0) {
        float sc = expf(log_scales[tid]);
        sc = fminf(fmaxf(sc, 0.01f), 2.0f);
        g_invvar[tid] = -0.5f / (sc * sc + 1e-8f);
        float am = expf(log_amps[tid]);
        g_amps[tid] = fminf(fmaxf(am, 1e-6f), 10.0f);
    }
}

// ---------------- prepack: fp32 matrix -> A-fragments (hi/lo) ----------------
__global__ __launch_bounds__(256) void a_frag_prepack(const float* __restrict__ A,
                                                      uint4* __restrict__ HF,
                                                      uint4* __restrict__ LF, int K) {
    const int mt = blockIdx.x;
    const int ks = blockIdx.y * 8 + (threadIdx.x >> 5);
    const int lane = threadIdx.x & 31;
    const int r0 = mt * 16 + (lane >> 2);
    const int k0 = ks * 16 + (lane & 3) * 2;
    const float* base = A + (size_t)r0 * K + k0;
    float2 v0 = *(const float2*)base;
    float2 v1 = *(const float2*)(base + 8 * (size_t)K);
    float2 v2 = *(const float2*)(base + 8);
    float2 v3 = *(const float2*)(base + 8 * (size_t)K + 8);
    uint32_t h0, l0, h1, l1, h2, l2, h3, l3;
    split2(v0.x, v0.y, h0, l0);
    split2(v1.x, v1.y, h1, l1);
    split2(v2.x, v2.y, h2, l2);
    split2(v3.x, v3.y, h3, l3);
    size_t idx = ((size_t)mt * KF + ks) * 32 + lane;
    HF[idx] = make_uint4(h0, h1, h2, h3);
    LF[idx] = make_uint4(l0, l1, l2, l3);
}

// ---------------- prepack: fp32 matrix (rows=N of NT gemm) -> B-fragments ----------------
__global__ __launch_bounds__(256) void b_frag_prepack(const float* __restrict__ B,
                                                      uint4* __restrict__ F, int K) {
    const int nt = blockIdx.x;
    const int ks = blockIdx.y * 8 + (threadIdx.x >> 5);
    const int lane = threadIdx.x & 31;
    const int row = nt * 8 + (lane >> 2);
    const int k0 = ks * 16 + (lane & 3) * 2;
    const float* base = B + (size_t)row * K + k0;
    float2 v0 = *(const float2*)base;
    float2 v1 = *(const float2*)(base + 8);
    uint32_t h0, l0, h1, l1;
    split2(v0.x, v0.y, h0, l0);
    split2(v1.x, v1.y, h1, l1);
    F[((size_t)nt * KF + ks) * 32 + lane] = make_uint4(h0, h1, l0, l1);
}

// ---------------- GEMM: cp.async smem double-buffer, 4x4 warp tile, 2 blocks/SM ----------------
__global__ __launch_bounds__(256, 2) void mma_gemm_frag(const uint4* __restrict__ AfH,
                                                        const uint4* __restrict__ AfL,
                                                        const uint4* __restrict__ Bf,
                                                        float* __restrict__ C, int M,
                                                        int vsplit_bx) {
    __shared__ uint4 sAh[2][8][32];    // 8KB
    __shared__ uint4 sAl[2][8][32];    // 8KB
    __shared__ uint4 sB[2][16][32];    // 16KB

    const int tid = threadIdx.x;
    const int warp = tid >> 5;
    const int lane = tid & 31;
    const int wm = warp >> 2;
    const int wn = warp & 3;
    const int mtb = blockIdx.y * 8;
    const int ntb = blockIdx.x * 16;
    const bool three = (int)blockIdx.x < vsplit_bx;

    float acc[4][4][4];
#pragma unroll
    for (int i = 0; i < 4; i++)
#pragma unroll
        for (int j = 0; j < 4; j++)
#pragma unroll
            for (int r = 0; r < 4; r++) acc[i][j][r] = 0.f;

    // cooperative stage loader: thread handles 4 of the 1024 16B words
    const int t0 = tid >> 5;       // 0..7
    const int tl = tid & 31;
    const size_t AST = (size_t)KF * 32;

    auto load_stage = [&](int s, int ks) {
        // A-hi: tiles 0..7, this thread does tile t0, lane tl
        cp_async16(smem_u32(&sAh[s][t0][tl]), AfH + ((size_t)(mtb + t0) * KF + ks) * 32 + tl);
        if (three)
            cp_async16(smem_u32(&sAl[s][t0][tl]), AfL + ((size_t)(mtb + t0) * KF + ks) * 32 + tl);
        // B: tiles 0..15, threads cover 2 tiles each (t0 and t0+8)
        cp_async16(smem_u32(&sB[s][t0][tl]), Bf + ((size_t)(ntb + t0) * KF + ks) * 32 + tl);
        cp_async16(smem_u32(&sB[s][t0 + 8][tl]), Bf + ((size_t)(ntb + t0 + 8) * KF + ks) * 32 + tl);
    };

    load_stage(0, 0);
    CP_COMMIT();

    for (int ks = 0; ks < KF; ks++) {
        const int buf = ks & 1;
        if (ks + 1 < KF) load_stage(buf ^ 1, ks + 1);
        CP_COMMIT();
        CP_WAIT1();
        __syncthreads();

        // consume: bb once, a-tiles streamed
        uint4 bb[4];
#pragma unroll
        for (int j = 0; j < 4; j++) bb[j] = sB[buf][wn * 4 + j][lane];
#pragma unroll
        for (int i = 0; i < 4; i++) {
            uint4 a4 = sAh[buf][wm * 4 + i][lane];
            uint32_t Ah[4] = {a4.x, a4.y, a4.z, a4.w};
#pragma unroll
            for (int j = 0; j < 4; j++) {
                uint32_t Bh[2] = {bb[j].x, bb[j].y};
                uint32_t Bl[2] = {bb[j].z, bb[j].w};
                mma_f16(acc[i][j], Ah, Bh);
                mma_f16(acc[i][j], Ah, Bl);
            }
            if (three) {
                uint4 l4 = sAl[buf][wm * 4 + i][lane];
                uint32_t Al[4] = {l4.x, l4.y, l4.z, l4.w};
#pragma unroll
                for (int j = 0; j < 4; j++) {
                    uint32_t Bh[2] = {bb[j].x, bb[j].y};
                    mma_f16(acc[i][j], Al, Bh);
                }
            }
        }
        __syncthreads();   // all warps done with buf before it is reloaded next iter
    }

#pragma unroll
    for (int i = 0; i < 4; i++) {
        int row0 = (mtb + wm * 4 + i) * 16 + (lane >> 2);
#pragma unroll
        for (int j = 0; j < 4; j++) {
            int col = (ntb + wn * 4 + j) * 8 + (lane & 3) * 2;
            *(float2*)(C + (size_t)row0 * M + col) = make_float2(acc[i][j][0], acc[i][j][1]);
            *(float2*)(C + (size_t)(row0 + 8) * M + col) = make_float2(acc[i][j][2], acc[i][j][3]);
        }
    }
}

// ---------------- splat gaussian weights ----------------
__global__ __launch_bounds__(256) void splat_weights_kernel() {
    __shared__ float sx[16][68];
    __shared__ float sc[16][68];
    const int tid = threadIdx.x;
    const int tb = blockIdx.x;
    const int h = blockIdx.y;
    const int b = blockIdx.z >> 1;
    const int which = blockIdx.z & 1;

    const int row = tid >> 4;
    const int d4 = (tid & 15) << 2;

    const int t = tb * 16 + row;
    float4 xv = *(const float4*)(g_qkv + ((size_t)(b * Tq + t) * 3 + which) * Dq + h * HDq + d4);
    *(float4*)&sx[row][d4] = xv;
    float4 cv = *(const float4*)(g_centers + (h * Sq + row) * HDq + d4);
    *(float4*)&sc[row][d4] = cv;
    __syncthreads();

    const int s = tid & 15;
    const int ti = tid >> 4;
    float acc = 0.f;
#pragma unroll
    for (int d = 0; d < 64; d++) {
        float diff = sx[ti][d] - sc[s][d];
        acc += diff * diff;
    }
    float w = __expf(acc * g_invvar[h * Sq + s]);
    if (which) w *= g_amps[h * Sq + s];
    float* dst = which ? g_kw : g_qw;
    dst[(((size_t)b * Hq + h) * Tq + (tb * 16 + ti)) * Sq + s] = w;
}

// ---------------- V fragment precompute (fp16 hi only) ----------------
__global__ __launch_bounds__(256) void v_frag_kernel() {
    __shared__ float sv[64][68];
    const int kt = blockIdx.x, h = blockIdx.y, b = blockIdx.z;
    const int tid = threadIdx.x;

#pragma unroll
    for (int i = 0; i < 4; i++) {
        int idx = i * 256 + tid;
        int row = idx >> 4;
        int c4 = (idx & 15) << 2;
        float4 v = *(const float4*)(g_qkv + ((size_t)(b * Tq + kt * 64 + row) * 3 + 2) * Dq +
                                    h * 64 + c4);
        *(float4*)&sv[row][c4] = v;
    }
    __syncthreads();

    uint2* dst = g_vfrag + (((size_t)(b * Hq + h) * 32 + kt) << 10);
#pragma unroll
    for (int i = 0; i < 4; i++) {
        int w = i * 256 + tid;
        int ks = w >> 8, rest = w & 255, nt = rest >> 5, lane = rest & 31;
        int d = nt * 8 + (lane >> 2);
        int k0 = ks * 16 + (lane & 3) * 2;
        uint32_t h0 = pack_f16x2(sv[k0][d], sv[k0 + 1][d]);
        uint32_t h1 = pack_f16x2(sv[k0 + 8][d], sv[k0 + 9][d]);
        dst[w] = make_uint2(h0, h1);
    }
}

// ---------------- KW fragment precompute ----------------
__global__ __launch_bounds__(256) void kw_frag_kernel() {
    const int kt = blockIdx.x, h = blockIdx.y, b = blockIdx.z;
    const int tid = threadIdx.x;
    const int nt = tid >> 5, lane = tid & 31;
    const float* kw = g_kw + (((size_t)b * Hq + h) * Tq + kt * 64 + nt * 8 + (lane >> 2)) * Sq;
    const int s0 = (lane & 3) * 2;
    uint32_t h0, l0, h1, l1;
    split2(__ldg(kw + s0), __ldg(kw + s0 + 1), h0, l0);
    split2(__ldg(kw + s0 + 8), __ldg(kw + s0 + 9), h1, l1);
    g_kwfrag[(((size_t)(b * Hq + h) * 32 + kt) << 8) + tid] = make_uint4(h0, h1, l0, l1);
}

// ---------------- flash attention: 1 query tile per warp (R12 exact) ----------------
__global__ __launch_bounds__(128, 6) void flash_mma(const float* __restrict__ temperature) {
    const int tid = threadIdx.x;
    const int warp = tid >> 5;
    const int lane = tid & 31;
    const int qt = blockIdx.x, h = blockIdx.y, b = blockIdx.z;

    const float temp = fminf(fmaxf(*temperature, 0.1f), 10.0f);
    const float LOG2E = 1.4426950408889634f;
    const float qscale = LOG2E / temp;
    float asum = 0.f;
#pragma unroll
    for (int s = 0; s < 16; s++) asum += g_amps[h * 16 + s];
    const float bound2 = asum * qscale;
    const float off2 = fmaxf(bound2 - 10.0f, 0.f);   // p = 2^(l2-off2) <= 2^10, fp16-safe

    const int r = lane >> 2;
    const int scp = (lane & 3) << 1;
    const int q0 = qt * 64 + warp * 16 + r;

    uint32_t qhi[4], qlo[4];
    {
        const float* qwp = g_qw + (((size_t)b * Hq + h) * Tq + q0) * Sq;
        float2 v;
        v = *(const float2*)(qwp + scp);
        split2(v.x * qscale, v.y * qscale, qhi[0], qlo[0]);
        v = *(const float2*)(qwp + 8 * Sq + scp);
        split2(v.x * qscale, v.y * qscale, qhi[1], qlo[1]);
        v = *(const float2*)(qwp + scp + 8);
        split2(v.x * qscale, v.y * qscale, qhi[2], qlo[2]);
        v = *(const float2*)(qwp + 8 * Sq + scp + 8);
        split2(v.x * qscale, v.y * qscale, qhi[3], qlo[3]);
    }

    float acc[8][4];
#pragma unroll
    for (int nt = 0; nt < 8; nt++)
#pragma unroll
        for (int i = 0; i < 4; i++) acc[nt][i] = 0.f;
    float ls0 = 0.f, ls1 = 0.f;

    const uint4* kwf = g_kwfrag + (((size_t)(b * Hq + h)) << 13) + lane;
    const uint2* vfb = g_vfrag + (((size_t)(b * Hq + h)) << 15) + lane;

    for (int kt = 0; kt < 32; kt++) {
        const uint4* kf = kwf + kt * 256;
        const uint2* vf = vfb + kt * 1024;
#pragma unroll
        for (int ks = 0; ks < 4; ks++) {
            uint32_t ap[4];
#pragma unroll
            for (int ntl = 0; ntl < 2; ntl++) {
                uint4 f = __ldg(kf + (ks * 2 + ntl) * 32);
                uint32_t bh[2] = {f.x, f.y};
                uint32_t bl[2] = {f.z, f.w};
                float c4[4] = {0.f, 0.f, 0.f, 0.f};
                mma_f16(c4, qhi, bh);
                mma_f16(c4, qhi, bl);
                mma_f16(c4, qlo, bh);
                float p0 = ex2_approx(c4[0] - off2);
                float p1 = ex2_approx(c4[1] - off2);
                float p2 = ex2_approx(c4[2] - off2);
                float p3 = ex2_approx(c4[3] - off2);
                ls0 += p0 + p1;
                ls1 += p2 + p3;
                ap[ntl * 2] = pack_f16x2(p0, p1);
                ap[ntl * 2 + 1] = pack_f16x2(p2, p3);
            }
#pragma unroll
            for (int nt = 0; nt < 8; nt++) {
                uint2 f = __ldg(vf + (ks * 8 + nt) * 32);
                uint32_t bh2[2] = {f.x, f.y};
                mma_f16(acc[nt], ap, bh2);
            }
        }
    }

    ls0 += __shfl_xor_sync(0xffffffffu, ls0, 1);
    ls0 += __shfl_xor_sync(0xffffffffu, ls0, 2);
    ls1 += __shfl_xor_sync(0xffffffffu, ls1, 1);
    ls1 += __shfl_xor_sync(0xffffffffu, ls1, 2);
    float inv0 = 1.0f / ls0, inv1 = 1.0f / ls1;

    // emit attn (hi-only fp16) in A-fragment order for the out-GEMM
    int mt = b * 128 + qt * 4 + warp;
#pragma unroll
    for (int ks = 0; ks < 4; ks++) {
        uint32_t h0 = pack_f16x2(acc[2 * ks][0] * inv0, acc[2 * ks][1] * inv0);
        uint32_t h1 = pack_f16x2(acc[2 * ks][2] * inv1, acc[2 * ks][3] * inv1);
        uint32_t h2 = pack_f16x2(acc[2 * ks + 1][0] * inv0, acc[2 * ks + 1][1] * inv0);
        uint32_t h3 = pack_f16x2(acc[2 * ks + 1][2] * inv1, acc[2 * ks + 1][3] * inv1);
        size_t idx = ((size_t)mt * KF + h * 4 + ks) * 32 + lane;
        g_afH[idx] = make_uint4(h0, h1, h2, h3);
    }
}

// ---------------- launch ----------------
// Order keeps mma_gemm_frag (gemm1) in the ncu-profiled 4th slot.
extern "C" void kernel_launch(void* const* d_in, const int* in_sizes, int n_in,
                              void* d_out, int out_size) {
    const float* x           = (const float*)d_in[0];
    const float* centers     = (const float*)d_in[1];
    const float* deltas      = (const float*)d_in[2];
    const float* log_scales  = (const float*)d_in[3];
    const float* log_amps    = (const float*)d_in[4];
    const float* movement    = (const float*)d_in[5];
    const float* temperature = (const float*)d_in[6];
    const float* qkv_w       = (const float*)d_in[7];
    const float* out_w       = (const float*)d_in[8];
    float* out = (float*)d_out;

    void *p_qkv = nullptr, *p_xfH = nullptr, *p_xfL = nullptr, *p_afH = nullptr,
         *p_wqkv = nullptr, *p_wo = nullptr;
    cudaGetSymbolAddress(&p_qkv, g_qkv);
    cudaGetSymbolAddress(&p_xfH, g_xfH);
    cudaGetSymbolAddress(&p_xfL, g_xfL);
    cudaGetSymbolAddress(&p_afH, g_afH);
    cudaGetSymbolAddress(&p_wqkv, g_wqkvf);
    cudaGetSymbolAddress(&p_wo, g_wof);
    float* qkv_buf = (float*)p_qkv;

    a_frag_prepack<<<dim3(256, 8), 256>>>(x, (uint4*)p_xfH, (uint4*)p_xfL, Dq);
    b_frag_prepack<<<dim3(384, 8), 256>>>(qkv_w, (uint4*)p_wqkv, Dq);
    prep_kernel<<<64, 256>>>(centers, deltas, log_scales, log_amps, movement);

    // (4) gemm1 — profiled slot
    mma_gemm_frag<<<dim3(3072 / 128, 4096 / 128), 256>>>(
        (const uint4*)p_xfH, (const uint4*)p_xfL, (const uint4*)p_wqkv, qkv_buf, 3 * Dq, 16);

    b_frag_prepack<<<dim3(128, 8), 256>>>(out_w, (uint4*)p_wo, Dq);
    v_frag_kernel<<<dim3(32, Hq, Bq), 256>>>();
    splat_weights_kernel<<<dim3(Tq / 16, Hq, Bq * 2), 256>>>();
    kw_frag_kernel<<<dim3(32, Hq, Bq), 256>>>();

    flash_mma<<<dim3(Tq / 64, Hq, Bq), 128>>>(temperature);

    // out = attn @ out_w.T : all 2-product (A hi-only from flash)
    mma_gemm_frag<<<dim3(1024 / 128, 4096 / 128), 256>>>(
        (const uint4*)p_afH, (const uint4*)p_afH, (const uint4*)p_wo, out, Dq, 0);
}